// round 16
// baseline (speedup 1.0000x reference)
#include <cuda_runtime.h>
#include <cuda_fp16.h>
#include <cstdint>

#define DIM   4096
#define NITER 20
#define NBLK  148
#define NTHR  1024
#define NREP  4
#define CROWS 26     // rows kept in smem (guaranteed residency); 2 rows in L1
#define NRMAX 28

// Eh_sm + u_h + tail(p_sm 64 | spare)
#define SMEM_BYTES (CROWS * DIM * 2 + DIM * 2 + 512)

// Scratch (static __device__ arrays = allowed scratch)
__device__ __align__(16) __half g_Eh[(size_t)DIM * DIM];      // fp16 row-scaled E (rows 26,27 of each block)
__device__ __align__(16) float  g_usum[3][NREP][DIM];         // phase x replica colsums
__device__ unsigned int g_bar;

__global__ void reset_kernel() {
    int i = blockIdx.x * blockDim.x + threadIdx.x;
    if (i == 0) g_bar = 0u;
    if (i < 3 * NREP * DIM) ((float*)g_usum)[i] = 0.0f;
}

__device__ __forceinline__ float warp_sum(float s) {
    #pragma unroll
    for (int o = 16; o; o >>= 1) s += __shfl_down_sync(0xffffffffu, s, o);
    return s;
}

__device__ __forceinline__ float warp_sum_all(float s) {   // butterfly: all lanes get total
    #pragma unroll
    for (int o = 16; o; o >>= 1) s += __shfl_xor_sync(0xffffffffu, s, o);
    return s;
}

// fence-free grid barrier (no CCTL.IVALL -> L1D survives the whole kernel)
__device__ __forceinline__ void bar_arrive_release() {
    asm volatile("red.release.gpu.global.add.u32 [%0], 1;" :: "l"(&g_bar) : "memory");
}
__device__ __forceinline__ unsigned bar_poll_acquire() {
    unsigned v;
    asm volatile("ld.acquire.gpu.global.u32 %0, [%1];" : "=r"(v) : "l"(&g_bar) : "memory");
    return v;
}

// vectorized fire-and-forget reduction: 1 op per 4 columns
__device__ __forceinline__ void red_add_v4(float* dst, float4 a) {
    asm volatile("red.global.add.v4.f32 [%0], {%1, %2, %3, %4};"
                 :: "l"(dst), "f"(a.x), "f"(a.y), "f"(a.z), "f"(a.w) : "memory");
}

__device__ __forceinline__ __half2 h2(unsigned r) { return *reinterpret_cast<__half2*>(&r); }

__device__ __forceinline__ float4 cvt4(uint2 r) {
    float2 f0 = __half22float2(h2(r.x));
    float2 f1 = __half22float2(h2(r.y));
    return make_float4(f0.x, f0.y, f1.x, f1.y);
}

// g = -log(-log(noise+eps)+eps); returns exp(logit + g)
__device__ __forceinline__ float gumbel_exp(float logit, float noise) {
    const float EPS = 1e-10f;
    float y = noise + EPS;
    float u = y - 1.0f;
    float w;
    if (fabsf(u) < 0.125f) {
        float p = 1.0f + u * (-0.5f + u * (0.33333333f + u * (-0.25f
                   + u * (0.2f + u * (-0.16666667f + u * 0.14285715f)))));
        w = -(u * p);
    } else {
        w = -__logf(y);
    }
    float g = -__logf(w + EPS);
    return __expf(logit + g);
}

// thread's 4 columns of local row k (smem for k<CROWS, global/L1 otherwise)
__device__ __forceinline__ uint2 ldrow(const __half* __restrict__ Eh_sm,
                                       int k, int bid, int tid) {
    if (k < CROWS)
        return reinterpret_cast<const uint2*>(Eh_sm + (size_t)k * DIM)[tid];
    int row = k * NBLK + bid;
    if (row >= DIM) row = bid;     // clamped; contribution masked via v=0
    return reinterpret_cast<const uint2*>(g_Eh + (size_t)row * DIM)[tid];
}

__global__ __launch_bounds__(NTHR, 1)
void sinkhorn_kernel(const float* __restrict__ logits,
                     const float* __restrict__ noise,
                     float* __restrict__ out) {
    extern __shared__ __align__(16) unsigned char smraw[];
    __half* Eh_sm = reinterpret_cast<__half*>(smraw);                    // CROWS x DIM
    __half* u_h   = reinterpret_cast<__half*>(smraw + CROWS * DIM * 2);  // DIM
    float*  p_sm  = reinterpret_cast<float*>(smraw + CROWS * DIM * 2 + DIM * 2);  // 64

    const int tid  = threadIdx.x;
    const int bid  = blockIdx.x;
    const int lane = tid & 31;
    const int wid  = tid >> 5;
    const int nr   = (DIM - bid + NBLK - 1) / NBLK;   // 28 (bid<100) else 27
    const int rep  = bid & (NREP - 1);
    unsigned epoch = 0;

    auto gsync = [&]() {
        __syncthreads();
        ++epoch;
        if (tid == 0) {
            bar_arrive_release();
            const unsigned target = epoch * NBLK;
            while (bar_poll_acquire() < target) { }
        }
        __syncthreads();
    };

    // per-lane v from p_sm: lane k holds v_k = 1/(p_sm[2k]+p_sm[2k+1]) (0 if masked)
    auto lane_v = [&]() -> float {
        float s = p_sm[2 * lane] + p_sm[2 * lane + 1];
        return (lane < nr) ? __frcp_rn(s) : 0.0f;
    };

    // ========== setup: block-cooperative per row, 1 sync per row ==========
    {
        float4 acc = make_float4(0.f, 0.f, 0.f, 0.f);
        float4 l = reinterpret_cast<const float4*>(logits + (size_t)bid * DIM)[tid];
        float4 n = reinterpret_cast<const float4*>(noise  + (size_t)bid * DIM)[tid];
        for (int k = 0; k < nr; ++k) {
            float4 e;
            e.x = gumbel_exp(l.x, n.x);
            e.y = gumbel_exp(l.y, n.y);
            e.z = gumbel_exp(l.z, n.z);
            e.w = gumbel_exp(l.w, n.w);
            if (k + 1 < nr) {   // prefetch next row past the reduction
                const int nrow = (k + 1) * NBLK + bid;
                l = reinterpret_cast<const float4*>(logits + (size_t)nrow * DIM)[tid];
                n = reinterpret_cast<const float4*>(noise  + (size_t)nrow * DIM)[tid];
            }
            float s = warp_sum((e.x + e.y) + (e.z + e.w));
            if (lane == 0) p_sm[(k & 1) * 32 + wid] = s;
            __syncthreads();
            // redundant all-warp combine: parity double-buffer avoids a 2nd sync
            float t = warp_sum_all(p_sm[(k & 1) * 32 + lane]);
            const float vin = __frcp_rn(t);
            __half2 h0 = __floats2half2_rn(e.x * vin, e.y * vin);
            __half2 h1 = __floats2half2_rn(e.z * vin, e.w * vin);
            uint2 r;
            r.x = *reinterpret_cast<unsigned*>(&h0);
            r.y = *reinterpret_cast<unsigned*>(&h1);
            if (k < CROWS)
                reinterpret_cast<uint2*>(Eh_sm + (size_t)k * DIM)[tid] = r;
            else
                reinterpret_cast<uint2*>(g_Eh + (size_t)(k * NBLK + bid) * DIM)[tid] = r;
            float4 q = cvt4(r);    // accumulate quantized values (exact colsums)
            acc.x += q.x; acc.y += q.y; acc.z += q.z; acc.w += q.w;
        }
        red_add_v4(&g_usum[0][rep][4 * tid], acc);
    }
    gsync();

    // ================ 19 fused iterations ================
    for (int it = 0; it < NITER - 1; ++it) {
        const int rb = it % 3;
        const int wb = (it + 1) % 3;   // pre-zeroed
        const int zb = (it + 2) % 3;   // zeroed below by warps 28-31

        // u_h = fp16(1 / sum of replicas)   (L2 reads, bypass L1)
        {
            float4 a = __ldcg(reinterpret_cast<const float4*>(g_usum[rb][0]) + tid);
            float4 b = __ldcg(reinterpret_cast<const float4*>(g_usum[rb][1]) + tid);
            float4 c = __ldcg(reinterpret_cast<const float4*>(g_usum[rb][2]) + tid);
            float4 d = __ldcg(reinterpret_cast<const float4*>(g_usum[rb][3]) + tid);
            float sx = (a.x + b.x) + (c.x + d.x);
            float sy = (a.y + b.y) + (c.y + d.y);
            float sz = (a.z + b.z) + (c.z + d.z);
            float sw = (a.w + b.w) + (c.w + d.w);
            __half2 h0 = __floats2half2_rn(__frcp_rn(sx), __frcp_rn(sy));
            __half2 h1 = __floats2half2_rn(__frcp_rn(sz), __frcp_rn(sw));
            uint2 r;
            r.x = *reinterpret_cast<unsigned*>(&h0);
            r.y = *reinterpret_cast<unsigned*>(&h1);
            reinterpret_cast<uint2*>(u_h)[tid] = r;
        }
        __syncthreads();

        // ---- row pass: 28 warps, warp = (row pair p, column half h), HFMA2 ----
        // half-row = 2048 halves = 256 uint4; half h spans uint4 [h*256, h*256+256)
        if (wid < 28) {
            const int p = wid >> 1, h = wid & 1;
            const int r1 = p + 14;
            const uint4* u4 = reinterpret_cast<const uint4*>(u_h) + h * 256;
            const uint4* e0 = reinterpret_cast<const uint4*>(Eh_sm + (size_t)p * DIM) + h * 256;
            const uint4* e1;
            if (r1 < CROWS) {
                e1 = reinterpret_cast<const uint4*>(Eh_sm + (size_t)r1 * DIM) + h * 256;
            } else {
                int row1 = r1 * NBLK + bid;
                if (row1 >= DIM) row1 = bid;           // masked via v=0
                e1 = reinterpret_cast<const uint4*>(g_Eh + (size_t)row1 * DIM) + h * 256;
            }
            const __half2 z = __float2half2_rn(0.f);
            __half2 x0 = z, x1 = z, x2 = z, x3 = z;    // row p accumulators
            __half2 y0 = z, y1 = z, y2 = z, y3 = z;    // row r1 accumulators
            #pragma unroll
            for (int c = 0; c < 8; ++c) {
                const int idx = c * 32 + lane;
                uint4 u = u4[idx];
                uint4 a = e0[idx];
                uint4 b = e1[idx];
                x0 = __hfma2(h2(a.x), h2(u.x), x0);
                x1 = __hfma2(h2(a.y), h2(u.y), x1);
                x2 = __hfma2(h2(a.z), h2(u.z), x2);
                x3 = __hfma2(h2(a.w), h2(u.w), x3);
                y0 = __hfma2(h2(b.x), h2(u.x), y0);
                y1 = __hfma2(h2(b.y), h2(u.y), y1);
                y2 = __hfma2(h2(b.z), h2(u.z), y2);
                y3 = __hfma2(h2(b.w), h2(u.w), y3);
            }
            float2 fx0 = __half22float2(x0), fx1 = __half22float2(x1);
            float2 fx2 = __half22float2(x2), fx3 = __half22float2(x3);
            float2 fy0 = __half22float2(y0), fy1 = __half22float2(y1);
            float2 fy2 = __half22float2(y2), fy3 = __half22float2(y3);
            float s0 = ((fx0.x + fx0.y) + (fx1.x + fx1.y))
                     + ((fx2.x + fx2.y) + (fx3.x + fx3.y));
            float s1 = ((fy0.x + fy0.y) + (fy1.x + fy1.y))
                     + ((fy2.x + fy2.y) + (fy3.x + fy3.y));
            // fused dual reduction: one xor-16 each, then one shared 4-step chain
            s0 += __shfl_xor_sync(0xffffffffu, s0, 16);
            s1 += __shfl_xor_sync(0xffffffffu, s1, 16);
            float s = (lane < 16) ? s0 : s1;
            #pragma unroll
            for (int o = 8; o; o >>= 1) s += __shfl_xor_sync(0xffffffffu, s, o);
            if (lane == 0)  p_sm[p * 2 + h]  = s;   // total s0
            if (lane == 16) p_sm[r1 * 2 + h] = s;   // total s1
        } else {
            // warps 28-31: zero the stale replica buffer concurrently
            const int t = tid - 896;
            if (t < 111) {
                int i = bid * 111 + t;
                if (i < NREP * DIM) ((float*)g_usum[zb])[i] = 0.0f;
            }
        }
        __syncthreads();

        // ---- col pass: per-warp redundant v (lane k holds v_k), shfl broadcast ----
        {
            float v = lane_v();
            __half2 hv = __float2half2_rn(v);
            unsigned uv = *reinterpret_cast<unsigned*>(&hv);
            const __half2 z = __float2half2_rn(0.f);
            __half2 accA = z, accB = z;
            #pragma unroll
            for (int k = 0; k < NRMAX; ++k) {
                uint2 e = ldrow(Eh_sm, k, bid, tid);
                unsigned uvk = __shfl_sync(0xffffffffu, uv, k);
                __half2 vv = h2(uvk);          // 0 for the masked tail row
                accA = __hfma2(h2(e.x), vv, accA);
                accB = __hfma2(h2(e.y), vv, accB);
            }
            float2 fA = __half22float2(accA);
            float2 fB = __half22float2(accB);
            red_add_v4(&g_usum[wb][rep][4 * tid], make_float4(fA.x, fA.y, fB.x, fB.y));
        }
        gsync();
    }

    // ================ final: out = Ê * v * u  (fp32 path) ================
    {
        const int fb = (NITER - 1) % 3;
        float4 a = __ldcg(reinterpret_cast<const float4*>(g_usum[fb][0]) + tid);
        float4 b = __ldcg(reinterpret_cast<const float4*>(g_usum[fb][1]) + tid);
        float4 c = __ldcg(reinterpret_cast<const float4*>(g_usum[fb][2]) + tid);
        float4 d = __ldcg(reinterpret_cast<const float4*>(g_usum[fb][3]) + tid);
        const float ux = __frcp_rn((a.x + b.x) + (c.x + d.x));
        const float uy = __frcp_rn((a.y + b.y) + (c.y + d.y));
        const float uz = __frcp_rn((a.z + b.z) + (c.z + d.z));
        const float uw = __frcp_rn((a.w + b.w) + (c.w + d.w));
        const float vl = lane_v();             // p_sm still holds last row-pass partials
        for (int k = 0; k < nr; ++k) {
            const int row = k * NBLK + bid;
            float4 e = cvt4((k < CROWS)
                ? reinterpret_cast<const uint2*>(Eh_sm + (size_t)k * DIM)[tid]
                : reinterpret_cast<const uint2*>(g_Eh + (size_t)row * DIM)[tid]);
            const float vv = __shfl_sync(0xffffffffu, vl, k);
            float4 o;
            o.x = e.x * vv * ux;
            o.y = e.y * vv * uy;
            o.z = e.z * vv * uz;
            o.w = e.w * vv * uw;
            reinterpret_cast<float4*>(out + (size_t)row * DIM)[tid] = o;
        }
    }
}

extern "C" void kernel_launch(void* const* d_in, const int* in_sizes, int n_in,
                              void* d_out, int out_size) {
    const float* logits = (const float*)d_in[0];
    const float* noise  = (const float*)d_in[1];
    float* out = (float*)d_out;

    static bool configured = false;
    if (!configured) {
        cudaFuncSetAttribute(sinkhorn_kernel,
                             cudaFuncAttributeMaxDynamicSharedMemorySize, SMEM_BYTES);
        configured = true;
    }

    reset_kernel<<<48, 1024>>>();
    sinkhorn_kernel<<<NBLK, NTHR, SMEM_BYTES>>>(logits, noise, out);
}

// round 17
// speedup vs baseline: 1.0392x; 1.0392x over previous
#include <cuda_runtime.h>
#include <cuda_fp16.h>
#include <cstdint>

#define DIM   4096
#define NITER 20
#define NBLK  148
#define NTHR  1024
#define NREP  4
#define CROWS 14     // rows in smem; rows 14..27 live in L1 (fence-free barrier keeps L1 warm)
#define NRMAX 28

// Eh_sm + u_h + tail(v_sm 32 | p_sm 64 | vh2 32)
#define SMEM_BYTES (CROWS * DIM * 2 + DIM * 2 + 512)

// Scratch (static __device__ arrays = allowed scratch)
__device__ __align__(16) __half g_Eh[(size_t)DIM * DIM];      // fp16 row-scaled E (L1-resident rows)
__device__ __align__(16) float  g_usum[3][NREP][DIM];         // phase x replica colsums
__device__ unsigned int g_bar;

__global__ void reset_kernel() {
    int i = blockIdx.x * blockDim.x + threadIdx.x;
    if (i == 0) g_bar = 0u;
    if (i < 3 * NREP * DIM) ((float*)g_usum)[i] = 0.0f;
}

__device__ __forceinline__ float warp_sum(float s) {
    #pragma unroll
    for (int o = 16; o; o >>= 1) s += __shfl_down_sync(0xffffffffu, s, o);
    return s;
}

__device__ __forceinline__ float warp_sum_all(float s) {   // butterfly: all lanes get total
    #pragma unroll
    for (int o = 16; o; o >>= 1) s += __shfl_xor_sync(0xffffffffu, s, o);
    return s;
}

// fence-free grid barrier (no CCTL.IVALL -> L1D survives the whole kernel)
__device__ __forceinline__ void bar_arrive_release() {
    asm volatile("red.release.gpu.global.add.u32 [%0], 1;" :: "l"(&g_bar) : "memory");
}
__device__ __forceinline__ unsigned bar_poll_acquire() {
    unsigned v;
    asm volatile("ld.acquire.gpu.global.u32 %0, [%1];" : "=r"(v) : "l"(&g_bar) : "memory");
    return v;
}

// vectorized fire-and-forget reduction: 1 op per 4 columns
__device__ __forceinline__ void red_add_v4(float* dst, float4 a) {
    asm volatile("red.global.add.v4.f32 [%0], {%1, %2, %3, %4};"
                 :: "l"(dst), "f"(a.x), "f"(a.y), "f"(a.z), "f"(a.w) : "memory");
}

__device__ __forceinline__ __half2 h2(unsigned r) { return *reinterpret_cast<__half2*>(&r); }

__device__ __forceinline__ float4 cvt4(uint2 r) {
    float2 f0 = __half22float2(h2(r.x));
    float2 f1 = __half22float2(h2(r.y));
    return make_float4(f0.x, f0.y, f1.x, f1.y);
}

// g = -log(-log(noise+eps)+eps); returns exp(logit + g)
__device__ __forceinline__ float gumbel_exp(float logit, float noise) {
    const float EPS = 1e-10f;
    float y = noise + EPS;
    float u = y - 1.0f;
    float w;
    if (fabsf(u) < 0.125f) {
        float p = 1.0f + u * (-0.5f + u * (0.33333333f + u * (-0.25f
                   + u * (0.2f + u * (-0.16666667f + u * 0.14285715f)))));
        w = -(u * p);
    } else {
        w = -__logf(y);
    }
    float g = -__logf(w + EPS);
    return __expf(logit + g);
}

// thread's 4 columns of local row k (smem for k<CROWS, global/L1 otherwise)
__device__ __forceinline__ uint2 ldrow(const __half* __restrict__ Eh_sm,
                                       int k, int bid, int tid) {
    if (k < CROWS)
        return reinterpret_cast<const uint2*>(Eh_sm + (size_t)k * DIM)[tid];
    int row = k * NBLK + bid;
    if (row >= DIM) row = bid;     // clamped; contribution masked via v=0
    return reinterpret_cast<const uint2*>(g_Eh + (size_t)row * DIM)[tid];
}

__global__ __launch_bounds__(NTHR, 1)
void sinkhorn_kernel(const float* __restrict__ logits,
                     const float* __restrict__ noise,
                     float* __restrict__ out) {
    extern __shared__ __align__(16) unsigned char smraw[];
    __half* Eh_sm = reinterpret_cast<__half*>(smraw);                    // CROWS x DIM
    __half* u_h   = reinterpret_cast<__half*>(smraw + CROWS * DIM * 2);  // DIM
    float*  tailf = reinterpret_cast<float*>(smraw + CROWS * DIM * 2 + DIM * 2);
    float*    v_sm   = tailf;            // 32 fp32 (final pass)
    float*    p_sm   = tailf + 32;       // 64: setup [parity*32+wid]; iter [row*2+half]
    unsigned* vh2_sm = reinterpret_cast<unsigned*>(tailf + 96);   // 32 half2-splat v

    const int tid  = threadIdx.x;
    const int bid  = blockIdx.x;
    const int lane = tid & 31;
    const int wid  = tid >> 5;
    const int nr   = (DIM - bid + NBLK - 1) / NBLK;   // 28 (bid<100) else 27
    const int rep  = bid & (NREP - 1);
    unsigned epoch = 0;

    auto gsync = [&]() {
        __syncthreads();
        ++epoch;
        if (tid == 0) {
            bar_arrive_release();
            const unsigned target = epoch * NBLK;
            while (bar_poll_acquire() < target) { }
        }
        __syncthreads();
    };

    // ========== setup: block-cooperative per row, 1 sync per row ==========
    {
        float4 acc = make_float4(0.f, 0.f, 0.f, 0.f);
        float4 l = reinterpret_cast<const float4*>(logits + (size_t)bid * DIM)[tid];
        float4 n = reinterpret_cast<const float4*>(noise  + (size_t)bid * DIM)[tid];
        for (int k = 0; k < nr; ++k) {
            float4 e;
            e.x = gumbel_exp(l.x, n.x);
            e.y = gumbel_exp(l.y, n.y);
            e.z = gumbel_exp(l.z, n.z);
            e.w = gumbel_exp(l.w, n.w);
            if (k + 1 < nr) {   // prefetch next row past the reduction
                const int nrow = (k + 1) * NBLK + bid;
                l = reinterpret_cast<const float4*>(logits + (size_t)nrow * DIM)[tid];
                n = reinterpret_cast<const float4*>(noise  + (size_t)nrow * DIM)[tid];
            }
            float s = warp_sum((e.x + e.y) + (e.z + e.w));
            if (lane == 0) p_sm[(k & 1) * 32 + wid] = s;
            __syncthreads();
            // redundant all-warp combine: parity double-buffer avoids a 2nd sync
            float t = warp_sum_all(p_sm[(k & 1) * 32 + lane]);
            const float vin = __frcp_rn(t);
            __half2 h0 = __floats2half2_rn(e.x * vin, e.y * vin);
            __half2 h1 = __floats2half2_rn(e.z * vin, e.w * vin);
            uint2 r;
            r.x = *reinterpret_cast<unsigned*>(&h0);
            r.y = *reinterpret_cast<unsigned*>(&h1);
            if (k < CROWS)
                reinterpret_cast<uint2*>(Eh_sm + (size_t)k * DIM)[tid] = r;
            else
                reinterpret_cast<uint2*>(g_Eh + (size_t)(k * NBLK + bid) * DIM)[tid] = r;
            float4 q = cvt4(r);    // accumulate quantized values (exact colsums)
            acc.x += q.x; acc.y += q.y; acc.z += q.z; acc.w += q.w;
        }
        red_add_v4(&g_usum[0][rep][4 * tid], acc);
    }
    gsync();

    // ================ 19 fused iterations ================
    for (int it = 0; it < NITER - 1; ++it) {
        const int rb = it % 3;
        const int wb = (it + 1) % 3;   // pre-zeroed
        const int zb = (it + 2) % 3;   // zeroed below by warps 28-31

        // u_h = fp16(1 / sum of replicas)   (L2 reads, bypass L1)
        {
            float4 a = __ldcg(reinterpret_cast<const float4*>(g_usum[rb][0]) + tid);
            float4 b = __ldcg(reinterpret_cast<const float4*>(g_usum[rb][1]) + tid);
            float4 c = __ldcg(reinterpret_cast<const float4*>(g_usum[rb][2]) + tid);
            float4 d = __ldcg(reinterpret_cast<const float4*>(g_usum[rb][3]) + tid);
            float sx = (a.x + b.x) + (c.x + d.x);
            float sy = (a.y + b.y) + (c.y + d.y);
            float sz = (a.z + b.z) + (c.z + d.z);
            float sw = (a.w + b.w) + (c.w + d.w);
            __half2 h0 = __floats2half2_rn(__frcp_rn(sx), __frcp_rn(sy));
            __half2 h1 = __floats2half2_rn(__frcp_rn(sz), __frcp_rn(sw));
            uint2 r;
            r.x = *reinterpret_cast<unsigned*>(&h0);
            r.y = *reinterpret_cast<unsigned*>(&h1);
            reinterpret_cast<uint2*>(u_h)[tid] = r;
        }
        __syncthreads();

        // ---- row pass: 28 warps, warp = (row pair p, column half h), HFMA2 ----
        // row p streams from SMEM, row p+14 streams from L1 (dual-port)
        if (wid < 28) {
            const int p = wid >> 1, h = wid & 1;
            const int r1 = p + 14;
            int row1 = r1 * NBLK + bid;
            if (row1 >= DIM) row1 = bid;               // masked via v=0
            const uint4* u4 = reinterpret_cast<const uint4*>(u_h) + h * 256;
            const uint4* e0 = reinterpret_cast<const uint4*>(Eh_sm + (size_t)p * DIM) + h * 256;
            const uint4* e1 = reinterpret_cast<const uint4*>(g_Eh + (size_t)row1 * DIM) + h * 256;
            const __half2 z = __float2half2_rn(0.f);
            __half2 x0 = z, x1 = z, x2 = z, x3 = z;    // row p accumulators
            __half2 y0 = z, y1 = z, y2 = z, y3 = z;    // row r1 accumulators
            #pragma unroll
            for (int c = 0; c < 8; ++c) {
                const int idx = c * 32 + lane;
                uint4 u = u4[idx];
                uint4 a = e0[idx];
                uint4 b = e1[idx];
                x0 = __hfma2(h2(a.x), h2(u.x), x0);
                x1 = __hfma2(h2(a.y), h2(u.y), x1);
                x2 = __hfma2(h2(a.z), h2(u.z), x2);
                x3 = __hfma2(h2(a.w), h2(u.w), x3);
                y0 = __hfma2(h2(b.x), h2(u.x), y0);
                y1 = __hfma2(h2(b.y), h2(u.y), y1);
                y2 = __hfma2(h2(b.z), h2(u.z), y2);
                y3 = __hfma2(h2(b.w), h2(u.w), y3);
            }
            float2 fx0 = __half22float2(x0), fx1 = __half22float2(x1);
            float2 fx2 = __half22float2(x2), fx3 = __half22float2(x3);
            float2 fy0 = __half22float2(y0), fy1 = __half22float2(y1);
            float2 fy2 = __half22float2(y2), fy3 = __half22float2(y3);
            float s0 = ((fx0.x + fx0.y) + (fx1.x + fx1.y))
                     + ((fx2.x + fx2.y) + (fx3.x + fx3.y));
            float s1 = ((fy0.x + fy0.y) + (fy1.x + fy1.y))
                     + ((fy2.x + fy2.y) + (fy3.x + fy3.y));
            s0 = warp_sum(s0);
            s1 = warp_sum(s1);
            if (lane == 0) {
                p_sm[p * 2 + h]  = s0;
                p_sm[r1 * 2 + h] = s1;
            }
        } else {
            // warps 28-31: zero the stale replica buffer concurrently
            const int t = tid - 896;
            if (t < 111) {
                int i = bid * 111 + t;
                if (i < NREP * DIM) ((float*)g_usum[zb])[i] = 0.0f;
            }
        }
        __syncthreads();

        // combine halves: one warp, one add + rcp per row; v splatted to half2
        if (wid == 0 && lane < NRMAX) {
            float s = p_sm[2 * lane] + p_sm[2 * lane + 1];
            float v = (lane < nr) ? __frcp_rn(s) : 0.0f;
            v_sm[lane] = v;
            __half2 hv = __float2half2_rn(v);
            vh2_sm[lane] = *reinterpret_cast<unsigned*>(&hv);
        }
        __syncthreads();

        // ---- col pass: thread-per-4cols, 14 smem rows + 14 L1 rows, HFMA2 ----
        {
            const __half2 z = __float2half2_rn(0.f);
            __half2 accA = z, accB = z;
            #pragma unroll
            for (int k = 0; k < NRMAX; ++k) {
                uint2 e = ldrow(Eh_sm, k, bid, tid);
                __half2 vv = h2(vh2_sm[k]);    // 0 for the masked tail row
                accA = __hfma2(h2(e.x), vv, accA);
                accB = __hfma2(h2(e.y), vv, accB);
            }
            float2 fA = __half22float2(accA);
            float2 fB = __half22float2(accB);
            red_add_v4(&g_usum[wb][rep][4 * tid], make_float4(fA.x, fA.y, fB.x, fB.y));
        }
        gsync();
    }

    // ================ final: out = Ê * v * u  (fp32 path) ================
    {
        const int fb = (NITER - 1) % 3;
        float4 a = __ldcg(reinterpret_cast<const float4*>(g_usum[fb][0]) + tid);
        float4 b = __ldcg(reinterpret_cast<const float4*>(g_usum[fb][1]) + tid);
        float4 c = __ldcg(reinterpret_cast<const float4*>(g_usum[fb][2]) + tid);
        float4 d = __ldcg(reinterpret_cast<const float4*>(g_usum[fb][3]) + tid);
        const float ux = __frcp_rn((a.x + b.x) + (c.x + d.x));
        const float uy = __frcp_rn((a.y + b.y) + (c.y + d.y));
        const float uz = __frcp_rn((a.z + b.z) + (c.z + d.z));
        const float uw = __frcp_rn((a.w + b.w) + (c.w + d.w));
        for (int k = 0; k < nr; ++k) {
            const int row = k * NBLK + bid;
            float4 e = cvt4((k < CROWS)
                ? reinterpret_cast<const uint2*>(Eh_sm + (size_t)k * DIM)[tid]
                : reinterpret_cast<const uint2*>(g_Eh + (size_t)row * DIM)[tid]);
            const float vv = v_sm[k];
            float4 o;
            o.x = e.x * vv * ux;
            o.y = e.y * vv * uy;
            o.z = e.z * vv * uz;
            o.w = e.w * vv * uw;
            reinterpret_cast<float4*>(out + (size_t)row * DIM)[tid] = o;
        }
    }
}

extern "C" void kernel_launch(void* const* d_in, const int* in_sizes, int n_in,
                              void* d_out, int out_size) {
    const float* logits = (const float*)d_in[0];
    const float* noise  = (const float*)d_in[1];
    float* out = (float*)d_out;

    static bool configured = false;
    if (!configured) {
        cudaFuncSetAttribute(sinkhorn_kernel,
                             cudaFuncAttributeMaxDynamicSharedMemorySize, SMEM_BYTES);
        configured = true;
    }

    reset_kernel<<<48, 1024>>>();
    sinkhorn_kernel<<<NBLK, NTHR, SMEM_BYTES>>>(logits, noise, out);
}